// round 6
// baseline (speedup 1.0000x reference)
#include <cuda_runtime.h>
#include <cuda_bf16.h>
#include <stdint.h>

// ---------------- problem constants ----------------
#define BB 4
#define SS 4096
#define HH 1024
#define MT (BB * SS)
#define QT 32
#define NW 4
#define WK 512
#define LOG2G (-0.04580368961312758f)

// ---------------- smem: XOR-swizzled 64B rows ----------------
// int8 tiles: row = [hi k0-31 (cu0,1) | lo k0-31 (cu2,3)], 128 rows x 64B = 8KB
#define STG_I 16384              // A (8KB) + B (8KB) per stage
#define NSTG_I 4
#define SMEM_IMMA (NSTG_I * STG_I)   // 65536
// bf16 out-gemm stages (R5 layout)
#define OFF_AHI 0
#define OFF_ALO 8192
#define OFF_BHI 16384
#define OFF_BLO 24576
#define STG_B 32768
#define NSTG_B 3
#define SMEM_OUT (NSTG_B * STG_B)    // 98304

// ---------------- device scratch ----------------
__device__ __align__(16) int8_t g_x8h[(size_t)MT * HH];
__device__ __align__(16) int8_t g_x8l[(size_t)MT * HH];
__device__ __align__(16) int8_t g_w8h[(size_t)3 * HH * HH];
__device__ __align__(16) int8_t g_w8l[(size_t)3 * HH * HH];
__device__ __align__(16) int8_t g_q8h[(size_t)MT * HH];
__device__ __align__(16) int8_t g_q8l[(size_t)MT * HH];
__device__ __align__(16) int8_t g_k8h[(size_t)MT * HH];
__device__ __align__(16) int8_t g_k8l[(size_t)MT * HH];
__device__ __align__(16) float g_sx[MT];
__device__ __align__(16) float g_sw[3 * HH];
__device__ __align__(16) float g_sq[MT];
__device__ __align__(16) float g_sk[MT];
__device__ __align__(16) float g_q[(size_t)MT * HH];
__device__ __align__(16) float g_k[(size_t)MT * HH];
__device__ __align__(16) float g_v[(size_t)MT * HH];
__device__ __align__(16) __nv_bfloat16 g_vthi[(size_t)MT * HH];  // [b][h][s]
__device__ __align__(16) __nv_bfloat16 g_vtlo[(size_t)MT * HH];
__device__ __align__(16) __nv_bfloat16 g_shi[(size_t)BB * QT * 128 * WK];
__device__ __align__(16) __nv_bfloat16 g_slo[(size_t)BB * QT * 128 * WK];

// ---------------- helpers ----------------
__device__ __forceinline__ uint32_t smem_u32(const void* p) {
    uint32_t a;
    asm("{ .reg .u64 t; cvta.to.shared.u64 t, %1; cvt.u32.u64 %0, t; }"
        : "=r"(a) : "l"(p));
    return a;
}
__device__ __forceinline__ uint32_t swz(uint32_t row, uint32_t cu) {
    return row * 64u + ((cu ^ ((row >> 1) & 3u)) << 4);
}
#define CP16(dst, src) \
    asm volatile("cp.async.cg.shared.global [%0], [%1], 16;" :: "r"(dst), "l"(src))
#define CP_COMMIT() asm volatile("cp.async.commit_group;" ::: "memory")
#define CP_WAIT(n)  asm volatile("cp.async.wait_group %0;" :: "n"(n) : "memory")

__device__ __forceinline__ void ldsm_x4(uint32_t* r, uint32_t addr) {
    asm volatile("ldmatrix.sync.aligned.m8n8.x4.shared.b16 {%0,%1,%2,%3}, [%4];"
                 : "=r"(r[0]), "=r"(r[1]), "=r"(r[2]), "=r"(r[3]) : "r"(addr));
}
__device__ __forceinline__ void mma16816(float* d, const uint32_t* a, const uint32_t* b) {
    asm volatile(
        "mma.sync.aligned.m16n8k16.row.col.f32.bf16.bf16.f32 "
        "{%0,%1,%2,%3}, {%4,%5,%6,%7}, {%8,%9}, {%0,%1,%2,%3};"
        : "+f"(d[0]), "+f"(d[1]), "+f"(d[2]), "+f"(d[3])
        : "r"(a[0]), "r"(a[1]), "r"(a[2]), "r"(a[3]), "r"(b[0]), "r"(b[1]));
}
__device__ __forceinline__ void imma16832(int* d, const uint32_t* a, const uint32_t* b) {
    asm volatile(
        "mma.sync.aligned.m16n8k32.row.col.s32.s8.s8.s32 "
        "{%0,%1,%2,%3}, {%4,%5,%6,%7}, {%8,%9}, {%0,%1,%2,%3};"
        : "+r"(d[0]), "+r"(d[1]), "+r"(d[2]), "+r"(d[3])
        : "r"(a[0]), "r"(a[1]), "r"(a[2]), "r"(a[3]), "r"(b[0]), "r"(b[1]));
}
// Exact mask-split of two fp32 into bf16x2 hi (truncated) + bf16x2 lo (residual).
__device__ __forceinline__ void split2(float x, float y, uint32_t& hi, uint32_t& lo) {
    uint32_t xu = __float_as_uint(x), yu = __float_as_uint(y);
    hi = __byte_perm(xu, yu, 0x7632);
    float hx = __uint_as_float(xu & 0xFFFF0000u);
    float hy = __uint_as_float(yu & 0xFFFF0000u);
    __nv_bfloat162 l = __float22bfloat162_rn(make_float2(x - hx, y - hy));
    lo = reinterpret_cast<uint32_t&>(l);
}
__device__ __forceinline__ uint32_t pack8(int a, int b, int c, int d) {
    return (uint32_t)(a & 0xFF) | ((uint32_t)(b & 0xFF) << 8) |
           ((uint32_t)(c & 0xFF) << 16) | ((uint32_t)(d & 0xFF) << 24);
}

// ---------------- int8 K-chunk (k32): 48 IMMAs per warp (64m x 32n tile) ----
__device__ __forceinline__ void chunk_imma(uint32_t stA, uint32_t stB, int wm, int wn,
                                           int lane, int (*a11)[4], int (*amid)[4]) {
    uint32_t ahi[16], alo[16], bhi[8], blo[8];
    uint32_t ar = (uint32_t)(wm * 64 + (lane & 15));
    uint32_t cuh = (uint32_t)(lane >> 4);  // 0/1
    #pragma unroll
    for (int mt = 0; mt < 4; mt++) {
        ldsm_x4(ahi + 4 * mt, stA + swz(ar + 16 * mt, cuh));
        ldsm_x4(alo + 4 * mt, stA + swz(ar + 16 * mt, cuh + 2));
    }
    uint32_t br = (uint32_t)(wn * 32 + ((lane >> 4) & 1) * 8 + (lane & 7));
    uint32_t cub = (uint32_t)((lane >> 3) & 1);
    #pragma unroll
    for (int np = 0; np < 2; np++) {
        ldsm_x4(bhi + 4 * np, stB + swz(br + 16 * np, cub));
        ldsm_x4(blo + 4 * np, stB + swz(br + 16 * np, cub + 2));
    }
    #pragma unroll
    for (int nt = 0; nt < 4; nt++) {
        const uint32_t* bh = bhi + 2 * nt;
        const uint32_t* bl = blo + 2 * nt;
        #pragma unroll
        for (int mt = 0; mt < 4; mt++) imma16832(a11[mt * 4 + nt], ahi + 4 * mt, bh);
        #pragma unroll
        for (int mt = 0; mt < 4; mt++) imma16832(amid[mt * 4 + nt], ahi + 4 * mt, bl);
        #pragma unroll
        for (int mt = 0; mt < 4; mt++) imma16832(amid[mt * 4 + nt], alo + 4 * mt, bh);
    }
}

// Issue one int8 tile (128 rows x 32 k, hi+lo) via cp.async. 256 threads, 2 CP16 each.
__device__ __forceinline__ void issue_i8(uint32_t dst, const int8_t* hi, const int8_t* lo,
                                         int ld, int k0, int tid) {
    uint32_t row = (uint32_t)(tid >> 1), u = (uint32_t)(tid & 1);
    CP16(dst + swz(row, u), hi + (size_t)row * ld + k0 + u * 16);
    CP16(dst + swz(row, u + 2), lo + (size_t)row * ld + k0 + u * 16);
}

// Issue one bf16 tile (128 rows x 32 k) via cp.async, 128 threads (out gemm).
__device__ __forceinline__ void issue_tile(uint32_t dst, const __nv_bfloat16* src,
                                           size_t ld, int k0, int tid) {
    uint32_t row = (uint32_t)(tid >> 2), cu = (uint32_t)(tid & 3);
    #pragma unroll
    for (int h = 0; h < 4; h++) {
        uint32_t r = row + 32 * h;
        CP16(dst + swz(r, cu), src + (size_t)r * ld + k0 + cu * 8);
    }
}

// bf16 K-chunk (k32): 3 split terms, warp tile 64m x 64n, 192 HMMAs (out gemm).
__device__ __forceinline__ void compute_chunk(uint32_t st, int wm, int wn, int lane,
                                              float (*d)[4]) {
    #pragma unroll
    for (int ks = 0; ks < 2; ks++) {
        uint32_t ah[16], al[16], bh[16], bl[16];
        uint32_t ar = (uint32_t)(wm * 64 + (lane & 15));
        uint32_t acu = (uint32_t)(ks * 2 + (lane >> 4));
        #pragma unroll
        for (int mt = 0; mt < 4; mt++) {
            ldsm_x4(ah + 4 * mt, st + OFF_AHI + swz(ar + 16 * mt, acu));
            ldsm_x4(al + 4 * mt, st + OFF_ALO + swz(ar + 16 * mt, acu));
        }
        uint32_t br = (uint32_t)(wn * 64 + ((lane >> 4) & 1) * 8 + (lane & 7));
        uint32_t bcu = (uint32_t)(ks * 2 + ((lane >> 3) & 1));
        #pragma unroll
        for (int nt = 0; nt < 8; nt += 2) {
            ldsm_x4(bh + 2 * nt, st + OFF_BHI + swz(br + 8 * nt, bcu));
            ldsm_x4(bl + 2 * nt, st + OFF_BLO + swz(br + 8 * nt, bcu));
        }
        #pragma unroll
        for (int nt = 0; nt < 8; nt++) {
            #pragma unroll
            for (int mt = 0; mt < 4; mt++) mma16816(d[mt * 8 + nt], ah + 4 * mt, bh + 2 * nt);
            #pragma unroll
            for (int mt = 0; mt < 4; mt++) mma16816(d[mt * 8 + nt], ah + 4 * mt, bl + 2 * nt);
            #pragma unroll
            for (int mt = 0; mt < 4; mt++) mma16816(d[mt * 8 + nt], al + 4 * mt, bh + 2 * nt);
        }
    }
}

// ---------------- quantization: fp32 row (K=HH) -> 2-slice int8 + scale ---
__global__ __launch_bounds__(128) void quant_rows(const float* __restrict__ src,
                                                  int8_t* __restrict__ hi,
                                                  int8_t* __restrict__ lo,
                                                  float* __restrict__ scale) {
    __shared__ float red[4];
    size_t row = blockIdx.x;
    const float* r = src + row * HH;
    int t = threadIdx.x, lane = t & 31, wid = t >> 5;
    float4 v0 = *reinterpret_cast<const float4*>(r + t * 8);
    float4 v1 = *reinterpret_cast<const float4*>(r + t * 8 + 4);
    float mx = fmaxf(fmaxf(fmaxf(fabsf(v0.x), fabsf(v0.y)), fmaxf(fabsf(v0.z), fabsf(v0.w))),
                     fmaxf(fmaxf(fabsf(v1.x), fabsf(v1.y)), fmaxf(fabsf(v1.z), fabsf(v1.w))));
    #pragma unroll
    for (int o = 16; o; o >>= 1) mx = fmaxf(mx, __shfl_xor_sync(0xFFFFFFFFu, mx, o));
    if (lane == 0) red[wid] = mx;
    __syncthreads();
    mx = fmaxf(fmaxf(red[0], red[1]), fmaxf(red[2], red[3]));
    float inv = (mx > 0.f) ? 16256.f / mx : 0.f;
    if (t == 0) scale[row] = (mx > 0.f) ? mx * (1.f / 16256.f) : 1.f;
    float f[8] = {v0.x, v0.y, v0.z, v0.w, v1.x, v1.y, v1.z, v1.w};
    int H[8], L[8];
    #pragma unroll
    for (int i = 0; i < 8; i++) {
        float tq = f[i] * inv;
        int h = __float2int_rn(tq * 0.0078125f);
        H[i] = h;
        L[i] = __float2int_rn(tq - (float)h * 128.f);
    }
    *reinterpret_cast<uint2*>(hi + row * HH + t * 8) =
        make_uint2(pack8(H[0], H[1], H[2], H[3]), pack8(H[4], H[5], H[6], H[7]));
    *reinterpret_cast<uint2*>(lo + row * HH + t * 8) =
        make_uint2(pack8(L[0], L[1], L[2], L[3]), pack8(L[4], L[5], L[6], L[7]));
}

// Transpose + split V: g_v[b][s][h] -> g_vthi/lo [b][h][s]
__global__ __launch_bounds__(256) void vsplitT_kernel() {
    __shared__ float ts[32][33];
    int h0 = blockIdx.x * 32, s0 = blockIdx.y * 32, b = blockIdx.z;
    int t = threadIdx.x;
    int sl = t >> 3, h4 = (t & 7) * 4;
    float4 v = *reinterpret_cast<const float4*>(
        g_v + ((size_t)b * SS + s0 + sl) * HH + h0 + h4);
    ts[sl][h4] = v.x; ts[sl][h4 + 1] = v.y; ts[sl][h4 + 2] = v.z; ts[sl][h4 + 3] = v.w;
    __syncthreads();
    int hr = t >> 3, s4 = (t & 7) * 4;
    uint32_t h0p, l0p, h1p, l1p;
    split2(ts[s4][hr], ts[s4 + 1][hr], h0p, l0p);
    split2(ts[s4 + 2][hr], ts[s4 + 3][hr], h1p, l1p);
    size_t o = ((size_t)b * HH + h0 + hr) * SS + s0 + s4;
    *reinterpret_cast<uint2*>(g_vthi + o) = make_uint2(h0p, h1p);
    *reinterpret_cast<uint2*>(g_vtlo + o) = make_uint2(l0p, l1p);
}

// ---------------- kernel 1: projections (int8 IMMA) ----------------
__global__ __launch_bounds__(256, 1) void proj_imma(const float* __restrict__ bias, int which) {
    extern __shared__ char sm[];
    uint32_t smb = smem_u32(sm);
    int tid = threadIdx.x, lane = tid & 31, wid = tid >> 5;
    int wm = wid & 1, wn = wid >> 1;
    int m0 = blockIdx.y * 128, n0 = blockIdx.x * 128;
    const int8_t* Ah = g_x8h + (size_t)m0 * HH;
    const int8_t* Al = g_x8l + (size_t)m0 * HH;
    const int8_t* Bh = g_w8h + (size_t)which * HH * HH + (size_t)n0 * HH;
    const int8_t* Bl = g_w8l + (size_t)which * HH * HH + (size_t)n0 * HH;
    const float* sb = g_sw + which * HH;

    int a11[16][4], amid[16][4];
    #pragma unroll
    for (int i = 0; i < 16; i++)
        #pragma unroll
        for (int j = 0; j < 4; j++) { a11[i][j] = 0; amid[i][j] = 0; }

    const int NC = HH / 32;  // 32
    #pragma unroll 1
    for (int p = 0; p < 3; p++) {
        uint32_t st = smb + p * STG_I;
        issue_i8(st, Ah, Al, HH, p * 32, tid);
        issue_i8(st + 8192, Bh, Bl, HH, p * 32, tid);
        CP_COMMIT();
    }
    #pragma unroll 1
    for (int c = 0; c < NC; c++) {
        CP_WAIT(2);
        __syncthreads();
        if (c + 3 < NC) {
            uint32_t st = smb + ((c + 3) % NSTG_I) * STG_I;
            issue_i8(st, Ah, Al, HH, (c + 3) * 32, tid);
            issue_i8(st + 8192, Bh, Bl, HH, (c + 3) * 32, tid);
        }
        CP_COMMIT();
        uint32_t st = smb + (c % NSTG_I) * STG_I;
        chunk_imma(st, st + 8192, wm, wn, lane, a11, amid);
    }

    float* C = (which == 0) ? g_q : (which == 1) ? g_k : g_v;
    int tq = lane >> 2, tr = lane & 3;
    #pragma unroll
    for (int mt = 0; mt < 4; mt++) {
        int ml = wm * 64 + mt * 16 + tq;
        float sa0 = g_sx[m0 + ml], sa1 = g_sx[m0 + ml + 8];
        #pragma unroll
        for (int nt = 0; nt < 4; nt++) {
            int n = n0 + wn * 32 + nt * 8 + tr * 2;
            float sb0 = sb[n], sb1 = sb[n + 1];
            float b0 = bias ? bias[n] : 0.f, b1 = bias ? bias[n + 1] : 0.f;
            int* p11 = a11[mt * 4 + nt];
            int* pm = amid[mt * 4 + nt];
            float v00 = fmaf((float)p11[0], 16384.f, (float)pm[0] * 128.f) * (sa0 * sb0) + b0;
            float v01 = fmaf((float)p11[1], 16384.f, (float)pm[1] * 128.f) * (sa0 * sb1) + b1;
            float v10 = fmaf((float)p11[2], 16384.f, (float)pm[2] * 128.f) * (sa1 * sb0) + b0;
            float v11 = fmaf((float)p11[3], 16384.f, (float)pm[3] * 128.f) * (sa1 * sb1) + b1;
            *reinterpret_cast<float2*>(C + (size_t)(m0 + ml) * HH + n) = make_float2(v00, v01);
            *reinterpret_cast<float2*>(C + (size_t)(m0 + ml + 8) * HH + n) = make_float2(v10, v11);
        }
    }
}

// ---------------- kernel 2: windowed decayed scores (int8 IMMA) ----------
__global__ __launch_bounds__(256, 1) void score_imma() {
    int w = blockIdx.x, qt = blockIdx.y, b = blockIdx.z;
    int i0 = qt * 128, j0 = i0 + (w - (NW - 1)) * 128;
    int tid = threadIdx.x, lane = tid & 31, wid = tid >> 5;
    size_t tile = ((size_t)(b * QT + qt)) * 128 * WK;

    if (j0 < 0) {  // zero-fill out-of-range window tiles
        for (int i = tid; i < 128 * 16; i += 256) {
            int row = i >> 4, q = i & 15;
            size_t o = tile + (size_t)row * WK + w * 128 + q * 8;
            *reinterpret_cast<uint4*>(g_shi + o) = make_uint4(0, 0, 0, 0);
            *reinterpret_cast<uint4*>(g_slo + o) = make_uint4(0, 0, 0, 0);
        }
        return;
    }

    extern __shared__ char sm[];
    uint32_t smb = smem_u32(sm);
    int wm = wid & 1, wn = wid >> 1;
    const int8_t* Ah = g_q8h + ((size_t)b * SS + i0) * HH;
    const int8_t* Al = g_q8l + ((size_t)b * SS + i0) * HH;
    const int8_t* Bh = g_k8h + ((size_t)b * SS + j0) * HH;
    const int8_t* Bl = g_k8l + ((size_t)b * SS + j0) * HH;

    int a11[16][4], amid[16][4];
    #pragma unroll
    for (int i = 0; i < 16; i++)
        #pragma unroll
        for (int j = 0; j < 4; j++) { a11[i][j] = 0; amid[i][j] = 0; }

    const int NC = HH / 32;
    #pragma unroll 1
    for (int p = 0; p < 3; p++) {
        uint32_t st = smb + p * STG_I;
        issue_i8(st, Ah, Al, HH, p * 32, tid);
        issue_i8(st + 8192, Bh, Bl, HH, p * 32, tid);
        CP_COMMIT();
    }
    #pragma unroll 1
    for (int c = 0; c < NC; c++) {
        CP_WAIT(2);
        __syncthreads();
        if (c + 3 < NC) {
            uint32_t st = smb + ((c + 3) % NSTG_I) * STG_I;
            issue_i8(st, Ah, Al, HH, (c + 3) * 32, tid);
            issue_i8(st + 8192, Bh, Bl, HH, (c + 3) * 32, tid);
        }
        CP_COMMIT();
        uint32_t st = smb + (c % NSTG_I) * STG_I;
        chunk_imma(st, st + 8192, wm, wn, lane, a11, amid);
    }

    int tq = lane >> 2, tr = lane & 3;
    #pragma unroll
    for (int mt = 0; mt < 4; mt++) {
        #pragma unroll
        for (int nt = 0; nt < 4; nt++) {
            int ncol = wn * 32 + nt * 8 + tr * 2;
            int* p11 = a11[mt * 4 + nt];
            int* pm = amid[mt * 4 + nt];
            #pragma unroll
            for (int half = 0; half < 2; half++) {
                int ml = wm * 64 + mt * 16 + tq + half * 8;
                int i = i0 + ml;
                float sq = g_sq[(size_t)b * SS + i];
                int jj = j0 + ncol;
                float sk0 = g_sk[(size_t)b * SS + jj], sk1 = g_sk[(size_t)b * SS + jj + 1];
                float r0 = fmaf((float)p11[half * 2 + 0], 16384.f,
                                (float)pm[half * 2 + 0] * 128.f) * (sq * sk0);
                float r1 = fmaf((float)p11[half * 2 + 1], 16384.f,
                                (float)pm[half * 2 + 1] * 128.f) * (sq * sk1);
                int d0 = i - jj, d1 = i - jj - 1;
                float w0 = (d0 < 0) ? 0.f : exp2f(LOG2G * (float)d0);
                float w1 = (d1 < 0) ? 0.f : exp2f(LOG2G * (float)d1);
                uint32_t h, l;
                split2(r0 * w0, r1 * w1, h, l);
                size_t o = tile + (size_t)ml * WK + w * 128 + ncol;
                *reinterpret_cast<uint32_t*>(g_shi + o) = h;
                *reinterpret_cast<uint32_t*>(g_slo + o) = l;
            }
        }
    }
}

// ---------------- kernel 3: banded output GEMM O = S * V (bf16 3-term) ----
__global__ __launch_bounds__(128, 2) void out_hmma(float* __restrict__ out) {
    int nc = blockIdx.x, qt = blockIdx.y, b = blockIdx.z;
    int i0 = qt * 128, n0 = nc * 128, jbase = i0 - (NW - 1) * 128;
    int tid = threadIdx.x, lane = tid & 31, wid = tid >> 5;
    int wm = wid & 1, wn = wid >> 1;
    size_t tile = ((size_t)(b * QT + qt)) * 128 * WK;
    const __nv_bfloat16* Ahi = g_shi + tile;
    const __nv_bfloat16* Alo = g_slo + tile;
    const __nv_bfloat16* Vth = g_vthi + ((size_t)b * HH + n0) * SS;
    const __nv_bfloat16* Vtl = g_vtlo + ((size_t)b * HH + n0) * SS;

    extern __shared__ char sm[];
    uint32_t smb = smem_u32(sm);

    float d[32][4];
    #pragma unroll
    for (int i = 0; i < 32; i++)
        #pragma unroll
        for (int j = 0; j < 4; j++) d[i][j] = 0.f;

    auto issue_vt = [&](uint32_t st, int k0) {
        uint32_t row = (uint32_t)(tid >> 2), cu = (uint32_t)(tid & 3);
        int j = jbase + k0 + (int)cu * 8;
        if (j < 0) j = 0;  // S is zero there; value irrelevant
        #pragma unroll
        for (int h = 0; h < 4; h++) {
            uint32_t r = row + 32 * h;
            CP16(st + OFF_BHI + swz(r, cu), Vth + (size_t)r * SS + j);
            CP16(st + OFF_BLO + swz(r, cu), Vtl + (size_t)r * SS + j);
        }
    };

    const int NC = WK / 32;  // 16
    #pragma unroll 1
    for (int p = 0; p < 2; p++) {
        uint32_t st = smb + p * STG_B;
        issue_tile(st + OFF_AHI, Ahi, WK, p * 32, tid);
        issue_tile(st + OFF_ALO, Alo, WK, p * 32, tid);
        issue_vt(st, p * 32);
        CP_COMMIT();
    }
    #pragma unroll 1
    for (int c = 0; c < NC; c++) {
        if (c + 1 < NC) CP_WAIT(1); else CP_WAIT(0);
        __syncthreads();
        if (c + 2 < NC) {
            uint32_t st = smb + ((c + 2) % NSTG_B) * STG_B;
            int k0 = (c + 2) * 32;
            issue_tile(st + OFF_AHI, Ahi, WK, k0, tid);
            issue_tile(st + OFF_ALO, Alo, WK, k0, tid);
            issue_vt(st, k0);
            CP_COMMIT();
        }
        compute_chunk(smb + (c % NSTG_B) * STG_B, wm, wn, lane, d);
    }

    int tq = lane >> 2, tr = lane & 3;
    #pragma unroll
    for (int mt = 0; mt < 4; mt++)
        #pragma unroll
        for (int nt = 0; nt < 8; nt++) {
            int ml = wm * 64 + mt * 16 + tq;
            int n = n0 + wn * 64 + nt * 8 + tr * 2;
            float* dd = d[mt * 8 + nt];
            *reinterpret_cast<float2*>(out + ((size_t)b * SS + i0 + ml) * HH + n) =
                make_float2(dd[0], dd[1]);
            *reinterpret_cast<float2*>(out + ((size_t)b * SS + i0 + ml + 8) * HH + n) =
                make_float2(dd[2], dd[3]);
        }
}

// ---------------- host launcher ----------------
extern "C" void kernel_launch(void* const* d_in, const int* in_sizes, int n_in,
                              void* d_out, int out_size) {
    const float* x  = (const float*)d_in[0];
    const float* Wq = (const float*)d_in[1];
    const float* bq = (const float*)d_in[2];
    const float* Wk = (const float*)d_in[3];
    const float* bk = (const float*)d_in[4];
    const float* Wv = (const float*)d_in[5];
    float* out = (float*)d_out;

    cudaFuncSetAttribute(proj_imma, cudaFuncAttributeMaxDynamicSharedMemorySize, SMEM_IMMA);
    cudaFuncSetAttribute(score_imma, cudaFuncAttributeMaxDynamicSharedMemorySize, SMEM_IMMA);
    cudaFuncSetAttribute(out_hmma, cudaFuncAttributeMaxDynamicSharedMemorySize, SMEM_OUT);

    int8_t *xh, *xl, *wh, *wl, *qh, *ql, *kh, *kl;
    float *sx, *sw, *sq, *sk, *qf, *kf;
    cudaGetSymbolAddress((void**)&xh, g_x8h);
    cudaGetSymbolAddress((void**)&xl, g_x8l);
    cudaGetSymbolAddress((void**)&wh, g_w8h);
    cudaGetSymbolAddress((void**)&wl, g_w8l);
    cudaGetSymbolAddress((void**)&qh, g_q8h);
    cudaGetSymbolAddress((void**)&ql, g_q8l);
    cudaGetSymbolAddress((void**)&kh, g_k8h);
    cudaGetSymbolAddress((void**)&kl, g_k8l);
    cudaGetSymbolAddress((void**)&sx, g_sx);
    cudaGetSymbolAddress((void**)&sw, g_sw);
    cudaGetSymbolAddress((void**)&sq, g_sq);
    cudaGetSymbolAddress((void**)&sk, g_sk);
    cudaGetSymbolAddress((void**)&qf, g_q);
    cudaGetSymbolAddress((void**)&kf, g_k);

    const size_t WSZ = (size_t)HH * HH;
    quant_rows<<<MT, 128>>>(x, xh, xl, sx);
    quant_rows<<<HH, 128>>>(Wq, wh, wl, sw);
    quant_rows<<<HH, 128>>>(Wk, wh + WSZ, wl + WSZ, sw + HH);
    quant_rows<<<HH, 128>>>(Wv, wh + 2 * WSZ, wl + 2 * WSZ, sw + 2 * HH);

    dim3 gproj(HH / 128, MT / 128);  // (8, 128)
    proj_imma<<<gproj, 256, SMEM_IMMA>>>(bq, 0);
    proj_imma<<<gproj, 256, SMEM_IMMA>>>(bk, 1);
    proj_imma<<<gproj, 256, SMEM_IMMA>>>(nullptr, 2);

    quant_rows<<<MT, 128>>>(qf, qh, ql, sq);
    quant_rows<<<MT, 128>>>(kf, kh, kl, sk);

    dim3 gvt(HH / 32, SS / 32, BB);
    vsplitT_kernel<<<gvt, 256>>>();

    dim3 gscore(NW, QT, BB);  // (4, 32, 4)
    score_imma<<<gscore, 256, SMEM_IMMA>>>();

    dim3 gout(HH / 128, QT, BB);  // (8, 32, 4)
    out_hmma<<<gout, 128, SMEM_OUT>>>(out);
}